// round 5
// baseline (speedup 1.0000x reference)
#include <cuda_runtime.h>
#include <cuda_bf16.h>
#include <math.h>

#define Bc      8
#define Nc      1024
#define Mc      512
#define Dc      128
#define Lc      6
#define DFFc    512
#define Sc      1536
#define HDc     16
#define MAXNB   64
#define ROWS    12288
#define PER_L   196608
#define NCTA    148

// ---------------- device globals --------------------------------------------
__device__ float g_x  [ROWS * Dc];
__device__ float g_qkv[ROWS * 384];
__device__ float g_te [Bc * Dc];
__device__ float g_nodes[ROWS];
__device__ int   g_adj[Sc * MAXNB];
__device__ int   g_adjcnt[Sc];
__device__ unsigned g_bar;

__device__ __nv_bfloat16 g_wThi[Lc * PER_L];
__device__ __nv_bfloat16 g_wTlo[Lc * PER_L];
__device__ __nv_bfloat16 g_ohi[ROWS * Dc];
__device__ __nv_bfloat16 g_olo[ROWS * Dc];
__device__ __nv_bfloat16 g_fhi[ROWS * DFFc];
__device__ __nv_bfloat16 g_flo[ROWS * DFFc];

__device__ __forceinline__ void split_bf16(float v, __nv_bfloat16& hi, __nv_bfloat16& lo) {
    hi = __float2bfloat16_rn(v);
    lo = __float2bfloat16_rn(v - __bfloat162float(hi));
}
__device__ __forceinline__ unsigned pack2hi(float a, float b) {
    __nv_bfloat162 p; p.x = __float2bfloat16_rn(a); p.y = __float2bfloat16_rn(b);
    return *(unsigned*)&p;
}
__device__ __forceinline__ unsigned pack2lo(float a, float b) {
    __nv_bfloat162 p;
    p.x = __float2bfloat16_rn(a - __bfloat162float(__float2bfloat16_rn(a)));
    p.y = __float2bfloat16_rn(b - __bfloat162float(__float2bfloat16_rn(b)));
    return *(unsigned*)&p;
}

// ---------------- grid barrier (persistent kernel) ---------------------------
__device__ __forceinline__ void gsync(int& bstep) {
    bstep++;
    unsigned target = (unsigned)bstep * NCTA;
    __threadfence();                 // release: flush my writes, IVALL L1
    __syncthreads();
    if (threadIdx.x == 0) {
        atomicAdd(&g_bar, 1u);
        while (*(volatile unsigned*)&g_bar < target) __nanosleep(64);
    }
    __syncthreads();
    __threadfence();                 // acquire: invalidate stale L1 lines
}

// ---------------- smem layout for GEMM ---------------------------------------
#define SW 68
#define A_WORDS (128 * SW)
#define B_WORDS (64 * SW)
#define SMEMB ((2 * A_WORDS + 2 * B_WORDS) * 4)

__device__ __forceinline__ void mma_bf16(float* c, const unsigned* a, const unsigned* b) {
    asm volatile(
        "mma.sync.aligned.m16n8k16.row.col.f32.bf16.bf16.f32 "
        "{%0,%1,%2,%3}, {%4,%5,%6,%7}, {%8,%9}, {%0,%1,%2,%3};"
        : "+f"(c[0]), "+f"(c[1]), "+f"(c[2]), "+f"(c[3])
        : "r"(a[0]), "r"(a[1]), "r"(a[2]), "r"(a[3]), "r"(b[0]), "r"(b[1]));
}

// ---------------- GEMM stage (grid-strided tiles) ------------------------------
// AMODE: 0 = A from bf16 (Ahi,Alo); 1 = LN(x,g,b); 2 = LN(x,g,b)*te
// EPI:   0 = store fp32; 1 = residual add fp32; 2 = relu -> split bf16
template <int AMODE, int EPI>
__device__ void gemm_stage(
    int bid, unsigned* smw,
    const float* __restrict__ Xf,
    const __nv_bfloat16* __restrict__ Ahi, const __nv_bfloat16* __restrict__ Alo,
    const float* __restrict__ gg, const float* __restrict__ bb,
    const __nv_bfloat16* __restrict__ Bhi, const __nv_bfloat16* __restrict__ Blo,
    float* __restrict__ C, __nv_bfloat16* __restrict__ Chi, __nv_bfloat16* __restrict__ Clo,
    int K, int Nn)
{
    unsigned* sAhi = smw;
    unsigned* sAlo = sAhi + A_WORDS;
    unsigned* sBhi = sAlo + A_WORDS;
    unsigned* sBlo = sBhi + B_WORDS;

    const int tid = threadIdx.x;
    const int lane = tid & 31, warp = tid >> 5;
    const int wm = (warp >> 1) * 32, wn = (warp & 1) * 32;
    const int g = lane >> 2, q4 = lane & 3;
    const int nB = Nn >> 6;
    const int nTiles = nB * (ROWS / 128);

    float4 gv, bv;
    if (AMODE != 0) {
        gv = *(const float4*)&gg[lane * 4];
        bv = *(const float4*)&bb[lane * 4];
    }

    for (int t = bid; t < nTiles; t += NCTA) {
        int mBlk = t / nB, nBlk = t % nB;
        int rowBase = mBlk * 128, colBase = nBlk * 64;

        float acc[2][4][4];
        #pragma unroll
        for (int mt = 0; mt < 2; mt++)
            #pragma unroll
            for (int nt = 0; nt < 4; nt++)
                #pragma unroll
                for (int i = 0; i < 4; i++) acc[mt][nt][i] = 0.0f;

        float4 tv;
        if (AMODE == 2) {
            int bIdx = rowBase / Sc;
            tv = *(const float4*)&g_te[bIdx * Dc + lane * 4];
        }

        for (int kt = 0; kt < K; kt += 128) {
            __syncthreads();
            if (AMODE == 0) {
                #pragma unroll
                for (int i = 0; i < 8; i++) {
                    int tt = tid + i * 256;
                    int r = tt >> 4, c = tt & 15;
                    size_t goff = (size_t)(rowBase + r) * K + kt + c * 8;
                    *(uint4*)&sAhi[r * SW + c * 4] = *(const uint4*)(Ahi + goff);
                    *(uint4*)&sAlo[r * SW + c * 4] = *(const uint4*)(Alo + goff);
                }
            } else {
                #pragma unroll
                for (int p = 0; p < 16; p++) {
                    int r = warp * 16 + p;
                    float4 xv = *(const float4*)&Xf[(size_t)(rowBase + r) * 128 + lane * 4];
                    float s1 = xv.x + xv.y + xv.z + xv.w;
                    float s2 = xv.x * xv.x + xv.y * xv.y + xv.z * xv.z + xv.w * xv.w;
                    #pragma unroll
                    for (int o = 16; o > 0; o >>= 1) {
                        s1 += __shfl_xor_sync(0xffffffffu, s1, o);
                        s2 += __shfl_xor_sync(0xffffffffu, s2, o);
                    }
                    float mean = s1 * (1.0f / 128.0f);
                    float var  = s2 * (1.0f / 128.0f) - mean * mean;
                    float inv  = rsqrtf(var + 1e-5f);
                    float o0 = (xv.x - mean) * inv * gv.x + bv.x;
                    float o1 = (xv.y - mean) * inv * gv.y + bv.y;
                    float o2 = (xv.z - mean) * inv * gv.z + bv.z;
                    float o3 = (xv.w - mean) * inv * gv.w + bv.w;
                    if (AMODE == 2) { o0 *= tv.x; o1 *= tv.y; o2 *= tv.z; o3 *= tv.w; }
                    sAhi[r * SW + lane * 2]     = pack2hi(o0, o1);
                    sAhi[r * SW + lane * 2 + 1] = pack2hi(o2, o3);
                    sAlo[r * SW + lane * 2]     = pack2lo(o0, o1);
                    sAlo[r * SW + lane * 2 + 1] = pack2lo(o2, o3);
                }
            }
            #pragma unroll
            for (int i = 0; i < 4; i++) {
                int tt = tid + i * 256;
                int n = tt >> 4, c = tt & 15;
                size_t goff = (size_t)(colBase + n) * K + kt + c * 8;
                *(uint4*)&sBhi[n * SW + c * 4] = *(const uint4*)(Bhi + goff);
                *(uint4*)&sBlo[n * SW + c * 4] = *(const uint4*)(Blo + goff);
            }
            __syncthreads();

            #pragma unroll
            for (int ks = 0; ks < 8; ks++) {
                const int w0 = ks * 8 + q4;
                unsigned ah[2][4], al[2][4], bh[4][2], bl[4][2];
                #pragma unroll
                for (int mt = 0; mt < 2; mt++) {
                    int r0 = wm + mt * 16 + g;
                    ah[mt][0] = sAhi[r0 * SW + w0];
                    ah[mt][1] = sAhi[(r0 + 8) * SW + w0];
                    ah[mt][2] = sAhi[r0 * SW + w0 + 4];
                    ah[mt][3] = sAhi[(r0 + 8) * SW + w0 + 4];
                    al[mt][0] = sAlo[r0 * SW + w0];
                    al[mt][1] = sAlo[(r0 + 8) * SW + w0];
                    al[mt][2] = sAlo[r0 * SW + w0 + 4];
                    al[mt][3] = sAlo[(r0 + 8) * SW + w0 + 4];
                }
                #pragma unroll
                for (int nt = 0; nt < 4; nt++) {
                    int n0 = wn + nt * 8 + g;
                    bh[nt][0] = sBhi[n0 * SW + w0];
                    bh[nt][1] = sBhi[n0 * SW + w0 + 4];
                    bl[nt][0] = sBlo[n0 * SW + w0];
                    bl[nt][1] = sBlo[n0 * SW + w0 + 4];
                }
                #pragma unroll
                for (int mt = 0; mt < 2; mt++)
                    #pragma unroll
                    for (int nt = 0; nt < 4; nt++) {
                        mma_bf16(acc[mt][nt], ah[mt], bh[nt]);
                        mma_bf16(acc[mt][nt], ah[mt], bl[nt]);
                        mma_bf16(acc[mt][nt], al[mt], bh[nt]);
                    }
            }
        }

        #pragma unroll
        for (int mt = 0; mt < 2; mt++)
            #pragma unroll
            for (int nt = 0; nt < 4; nt++) {
                int r = rowBase + wm + mt * 16 + g;
                int c = colBase + wn + nt * 8 + q4 * 2;
                float* a = acc[mt][nt];
                if (EPI == 0) {
                    *(float2*)&C[(size_t)r * Nn + c]       = make_float2(a[0], a[1]);
                    *(float2*)&C[(size_t)(r + 8) * Nn + c] = make_float2(a[2], a[3]);
                } else if (EPI == 1) {
                    float2 v0 = *(const float2*)&C[(size_t)r * Nn + c];
                    float2 v1 = *(const float2*)&C[(size_t)(r + 8) * Nn + c];
                    v0.x += a[0]; v0.y += a[1]; v1.x += a[2]; v1.y += a[3];
                    *(float2*)&C[(size_t)r * Nn + c]       = v0;
                    *(float2*)&C[(size_t)(r + 8) * Nn + c] = v1;
                } else {
                    #pragma unroll
                    for (int rr = 0; rr < 2; rr++) {
                        float v0 = fmaxf(a[rr * 2 + 0], 0.0f);
                        float v1 = fmaxf(a[rr * 2 + 1], 0.0f);
                        size_t o = (size_t)(r + rr * 8) * Nn + c;
                        *(unsigned*)&Chi[o] = pack2hi(v0, v1);
                        *(unsigned*)&Clo[o] = pack2lo(v0, v1);
                    }
                }
            }
    }
}

// ---------------- init stage tasks ---------------------------------------------
__device__ void wsplit_task(int tn, float* s /* [32][33] */,
                            const float* Wq, const float* Wk, const float* Wv,
                            const float* Wo, const float* W1, const float* W2) {
    int l = tn / 192, tt = tn % 192;
    const float* src; int Nn, k0, n0; size_t dstBase; int dstLd;
    if (tt < 64) {
        int seg = tt >> 4, local = tt & 15;
        k0 = (local >> 2) * 32; n0 = (local & 3) * 32; Nn = 128; dstLd = 128;
        if      (seg == 0) { src = Wq + (size_t)l * 16384; dstBase = (size_t)l * PER_L; }
        else if (seg == 1) { src = Wk + (size_t)l * 16384; dstBase = (size_t)l * PER_L + 16384; }
        else if (seg == 2) { src = Wv + (size_t)l * 16384; dstBase = (size_t)l * PER_L + 32768; }
        else               { src = Wo + (size_t)l * 16384; dstBase = (size_t)l * PER_L + 49152; }
    } else if (tt < 128) {
        int local = tt - 64;
        k0 = (local >> 4) * 32; n0 = (local & 15) * 32; Nn = 512; dstLd = 128;
        src = W1 + (size_t)l * 65536; dstBase = (size_t)l * PER_L + 65536;
    } else {
        int local = tt - 128;
        k0 = (local >> 2) * 32; n0 = (local & 3) * 32; Nn = 128; dstLd = 512;
        src = W2 + (size_t)l * 65536; dstBase = (size_t)l * PER_L + 131072;
    }
    int tx = threadIdx.x & 31, ty = threadIdx.x >> 5;
    #pragma unroll
    for (int j = 0; j < 4; j++)
        s[(ty + j * 8) * 33 + tx] = src[(size_t)(k0 + ty + j * 8) * Nn + n0 + tx];
    __syncthreads();
    #pragma unroll
    for (int j = 0; j < 4; j++) {
        int n = n0 + ty + j * 8;
        float v = s[tx * 33 + ty + j * 8];
        __nv_bfloat16 hi, lo;
        split_bf16(v, hi, lo);
        size_t o = dstBase + (size_t)n * dstLd + k0 + tx;
        g_wThi[o] = hi;
        g_wTlo[o] = lo;
    }
    __syncthreads();
}

__device__ void nodes_task(int tn, const float* r_t, const int* pcm) {
    int w = tn * 8 + (threadIdx.x >> 5);
    int lane = threadIdx.x & 31;
    int b = w >> 9, m = w & 511;
    int cnt = 0;
    #pragma unroll
    for (int i = 0; i < 32; i++) {
        int col = lane + i * 32;
        bool pred = (pcm[(size_t)m * Nc + col] != 0) && (r_t[(size_t)b * Nc + col] < 0.0f);
        cnt += __popc(__ballot_sync(0xffffffffu, pred));
    }
    if (lane == 0) g_nodes[(size_t)b * Sc + Nc + m] = (float)(cnt & 1);
}

__device__ void adj_task(int tn, const int* pcm) {
    int s = tn * 8 + (threadIdx.x >> 5);
    int lane = threadIdx.x & 31;
    unsigned lt = (1u << lane) - 1u;
    int* adj = g_adj + s * MAXNB;
    int cnt = 1;
    if (lane == 0) adj[0] = s;
    if (s < Nc) {
        #pragma unroll
        for (int i = 0; i < 16; i++) {
            int m = lane + i * 32;
            bool pred = pcm[(size_t)m * Nc + s] != 0;
            unsigned bal = __ballot_sync(0xffffffffu, pred);
            int rank = __popc(bal & lt);
            if (pred && cnt + rank < MAXNB) adj[cnt + rank] = Nc + m;
            cnt += __popc(bal);
        }
    } else {
        const int* row = pcm + (size_t)(s - Nc) * Nc;
        #pragma unroll
        for (int i = 0; i < 32; i++) {
            int n = lane + i * 32;
            bool pred = row[n] != 0;
            unsigned bal = __ballot_sync(0xffffffffu, pred);
            int rank = __popc(bal & lt);
            if (pred && cnt + rank < MAXNB) adj[cnt + rank] = n;
            cnt += __popc(bal);
        }
    }
    if (lane == 0) g_adjcnt[s] = cnt < MAXNB ? cnt : MAXNB;
}

// ---------------- attention stage -----------------------------------------------
__device__ void attn_stage(int bid) {
    int h = threadIdx.x >> 5, lane = threadIdx.x & 31;
    for (int bs = bid; bs < ROWS; bs += NCTA) {
        int b = bs / Sc, s = bs % Sc;
        int cnt = g_adjcnt[s];

        const float* qp = g_qkv + (size_t)bs * 384 + h * HDc;
        float qr[HDc];
        #pragma unroll
        for (int d = 0; d < HDc; d++) qr[d] = qp[d];

        float sc0 = -1e30f, sc1 = -1e30f;
        int n0 = -1, n1 = -1;
        if (lane < cnt) {
            n0 = g_adj[s * MAXNB + lane];
            const float* kp = g_qkv + ((size_t)b * Sc + n0) * 384 + 128 + h * HDc;
            float dot = 0.0f;
            #pragma unroll
            for (int d = 0; d < HDc; d++) dot += qr[d] * kp[d];
            sc0 = dot * 0.25f;
        }
        if (lane + 32 < cnt) {
            n1 = g_adj[s * MAXNB + lane + 32];
            const float* kp = g_qkv + ((size_t)b * Sc + n1) * 384 + 128 + h * HDc;
            float dot = 0.0f;
            #pragma unroll
            for (int d = 0; d < HDc; d++) dot += qr[d] * kp[d];
            sc1 = dot * 0.25f;
        }

        float m = fmaxf(sc0, sc1);
        #pragma unroll
        for (int off = 16; off > 0; off >>= 1) m = fmaxf(m, __shfl_xor_sync(0xffffffffu, m, off));
        float p0 = (n0 >= 0) ? __expf(sc0 - m) : 0.0f;
        float p1 = (n1 >= 0) ? __expf(sc1 - m) : 0.0f;
        float ps = p0 + p1;
        #pragma unroll
        for (int off = 16; off > 0; off >>= 1) ps += __shfl_xor_sync(0xffffffffu, ps, off);

        float acc[HDc] = {};
        if (n0 >= 0) {
            const float* vp = g_qkv + ((size_t)b * Sc + n0) * 384 + 256 + h * HDc;
            #pragma unroll
            for (int d = 0; d < HDc; d++) acc[d] += p0 * vp[d];
        }
        if (n1 >= 0) {
            const float* vp = g_qkv + ((size_t)b * Sc + n1) * 384 + 256 + h * HDc;
            #pragma unroll
            for (int d = 0; d < HDc; d++) acc[d] += p1 * vp[d];
        }
        #pragma unroll
        for (int d = 0; d < HDc; d++)
            #pragma unroll
            for (int off = 16; off > 0; off >>= 1)
                acc[d] += __shfl_xor_sync(0xffffffffu, acc[d], off);

        if (lane == 0) {
            float inv = 1.0f / ps;
            #pragma unroll
            for (int d = 0; d < HDc; d += 2) {
                float v0 = acc[d] * inv, v1 = acc[d + 1] * inv;
                size_t o = (size_t)bs * Dc + h * HDc + d;
                *(unsigned*)&g_ohi[o] = pack2hi(v0, v1);
                *(unsigned*)&g_olo[o] = pack2lo(v0, v1);
            }
        }
    }
}

// ---------------- megakernel ------------------------------------------------------
__global__ void __launch_bounds__(256)
k_mega(const float* __restrict__ r_t, const int* __restrict__ pcm,
       const float* __restrict__ src_embed,
       const float* __restrict__ Wq, const float* __restrict__ Wk,
       const float* __restrict__ Wv, const float* __restrict__ Wo,
       const float* __restrict__ W1, const float* __restrict__ W2,
       const float* __restrict__ g1, const float* __restrict__ b1,
       const float* __restrict__ g2, const float* __restrict__ b2,
       const float* __restrict__ fc_w, const float* __restrict__ fc_b,
       float* __restrict__ out)
{
    extern __shared__ unsigned smw[];
    const int bid = blockIdx.x;
    const int tid = threadIdx.x;
    int bstep = 0;

    // ---- stage 0: weight split + syndrome + adjacency (task list) ----
    for (int t = bid; t < 1152 + 512 + 192; t += NCTA) {
        if (t < 1152)       wsplit_task(t, (float*)smw, Wq, Wk, Wv, Wo, W1, W2);
        else if (t < 1664)  nodes_task(t - 1152, r_t, pcm);
        else                adj_task(t - 1664, pcm);
    }
    gsync(bstep);

    // ---- stage 1: x init ----
    for (int i = bid * 256 + tid; i < ROWS * Dc; i += NCTA * 256) {
        int d = i & 127;
        int bs = i >> 7;
        int b = bs / Sc, s = bs % Sc;
        float node = (s < Nc) ? fabsf(r_t[(size_t)b * Nc + s]) : g_nodes[bs];
        g_x[i] = src_embed[s * Dc + d] * node * g_te[b * Dc + d];
    }
    gsync(bstep);

    // ---- layers ----
    for (int l = 0; l < Lc; l++) {
        const __nv_bfloat16* lwh = g_wThi + (size_t)l * PER_L;
        const __nv_bfloat16* lwl = g_wTlo + (size_t)l * PER_L;

        gemm_stage<1, 0>(bid, smw, g_x, nullptr, nullptr, g1 + l * Dc, b1 + l * Dc,
                         lwh, lwl, g_qkv, nullptr, nullptr, 128, 384);
        gsync(bstep);
        attn_stage(bid);
        gsync(bstep);
        gemm_stage<0, 1>(bid, smw, nullptr, g_ohi, g_olo, nullptr, nullptr,
                         lwh + 49152, lwl + 49152, g_x, nullptr, nullptr, 128, 128);
        gsync(bstep);
        gemm_stage<2, 2>(bid, smw, g_x, nullptr, nullptr, g2 + l * Dc, b2 + l * Dc,
                         lwh + 65536, lwl + 65536, nullptr, g_fhi, g_flo, 128, 512);
        gsync(bstep);
        gemm_stage<0, 1>(bid, smw, nullptr, g_fhi, g_flo, nullptr, nullptr,
                         lwh + 131072, lwl + 131072, g_x, nullptr, nullptr, 512, 128);
        gsync(bstep);
    }

    // ---- output head ----
    {
        int warp = tid >> 5, lane = tid & 31;
        for (int row = bid * 8 + warp; row < ROWS; row += NCTA * 8) {
            float sum = 0.0f;
            #pragma unroll
            for (int d = lane; d < Dc; d += 32) sum += g_x[(size_t)row * Dc + d] * fc_w[d];
            #pragma unroll
            for (int off = 16; off > 0; off >>= 1) sum += __shfl_xor_sync(0xffffffffu, sum, off);
            if (lane == 0) out[row] = sum + fc_b[0];
        }
    }
}

// ---------------- tiny init: reset barrier + time embedding -----------------------
__global__ void k_init(const int* __restrict__ t, const float* __restrict__ time_table) {
    int i = blockIdx.x * blockDim.x + threadIdx.x;
    if (i == 0) g_bar = 0;
    if (i < Bc * Dc) {
        int b = i >> 7, d = i & 127;
        g_te[i] = time_table[t[b] * Dc + d];
    }
}

// ---------------- launcher ----------------------------------------------------------
extern "C" void kernel_launch(void* const* d_in, const int* in_sizes, int n_in,
                              void* d_out, int out_size) {
    const float* r_t        = (const float*)d_in[0];
    const int*   t          = (const int*)  d_in[1];
    const int*   pcm        = (const int*)  d_in[2];
    const float* src_embed  = (const float*)d_in[4];
    const float* time_table = (const float*)d_in[5];
    const float* Wq = (const float*)d_in[6];
    const float* Wk = (const float*)d_in[7];
    const float* Wv = (const float*)d_in[8];
    const float* Wo = (const float*)d_in[9];
    const float* W1 = (const float*)d_in[10];
    const float* W2 = (const float*)d_in[11];
    const float* g1 = (const float*)d_in[12];
    const float* b1 = (const float*)d_in[13];
    const float* g2 = (const float*)d_in[14];
    const float* b2 = (const float*)d_in[15];
    const float* fc_w = (const float*)d_in[16];
    const float* fc_b = (const float*)d_in[17];
    float* out = (float*)d_out;

    static int smemSet = 0;
    if (!smemSet) {
        cudaFuncSetAttribute(k_mega, cudaFuncAttributeMaxDynamicSharedMemorySize, SMEMB);
        smemSet = 1;
    }

    k_init<<<4, 256>>>(t, time_table);
    k_mega<<<NCTA, 256, SMEMB>>>(r_t, pcm, src_embed, Wq, Wk, Wv, Wo, W1, W2,
                                 g1, b1, g2, b2, fc_w, fc_b, out);
}

// round 7
// speedup vs baseline: 1.2976x; 1.2976x over previous
#include <cuda_runtime.h>
#include <cuda_bf16.h>
#include <math.h>

#define Bc      8
#define Nc      1024
#define Mc      512
#define Dc      128
#define Lc      6
#define DFFc    512
#define Sc      1536
#define HDc     16
#define MAXNB   64
#define ROWS    12288
#define PER_L   196608

// ---------------- scratch ------------------------------------------------------
__device__ float g_x  [ROWS * Dc];
__device__ float g_qkv[ROWS * 384];
__device__ float g_te [Bc * Dc];
__device__ float g_nodes[ROWS];
__device__ int   g_adj[Sc * MAXNB];
__device__ int   g_adjcnt[Sc];

__device__ __nv_bfloat16 g_wThi[Lc * PER_L];
__device__ __nv_bfloat16 g_wTlo[Lc * PER_L];
__device__ __nv_bfloat16 g_ohi[ROWS * Dc];
__device__ __nv_bfloat16 g_olo[ROWS * Dc];
__device__ __nv_bfloat16 g_fhi[ROWS * DFFc];
__device__ __nv_bfloat16 g_flo[ROWS * DFFc];

__device__ __forceinline__ void split_bf16(float v, __nv_bfloat16& hi, __nv_bfloat16& lo) {
    hi = __float2bfloat16_rn(v);
    lo = __float2bfloat16_rn(v - __bfloat162float(hi));
}
__device__ __forceinline__ unsigned pack2hi(float a, float b) {
    __nv_bfloat162 p; p.x = __float2bfloat16_rn(a); p.y = __float2bfloat16_rn(b);
    return *(unsigned*)&p;
}
__device__ __forceinline__ unsigned pack2lo(float a, float b) {
    __nv_bfloat162 p;
    p.x = __float2bfloat16_rn(a - __bfloat162float(__float2bfloat16_rn(a)));
    p.y = __float2bfloat16_rn(b - __bfloat162float(__float2bfloat16_rn(b)));
    return *(unsigned*)&p;
}

// ---------------- init ----------------------------------------------------------
__global__ void k_te(const int* __restrict__ t, const float* __restrict__ time_table) {
    int i = blockIdx.x * blockDim.x + threadIdx.x;
    if (i >= Bc * Dc) return;
    int b = i / Dc, d = i % Dc;
    g_te[i] = time_table[t[b] * Dc + d];
}

__global__ void k_nodes(const float* __restrict__ r_t, const int* __restrict__ pcm) {
    int w = blockIdx.x * 8 + (threadIdx.x >> 5);
    if (w >= Bc * Mc) return;
    int lane = threadIdx.x & 31;
    int b = w >> 9, m = w & 511;
    int cnt = 0;
    #pragma unroll
    for (int i = 0; i < 32; i++) {
        int col = lane + i * 32;
        bool pred = (pcm[(size_t)m * Nc + col] != 0) && (r_t[(size_t)b * Nc + col] < 0.0f);
        cnt += __popc(__ballot_sync(0xffffffffu, pred));
    }
    if (lane == 0) g_nodes[(size_t)b * Sc + Nc + m] = (float)(cnt & 1);
}

__global__ void k_adj(const int* __restrict__ pcm) {
    int s = blockIdx.x * 8 + (threadIdx.x >> 5);
    if (s >= Sc) return;
    int lane = threadIdx.x & 31;
    unsigned lt = (1u << lane) - 1u;
    int* adj = g_adj + s * MAXNB;
    int cnt = 1;
    if (lane == 0) adj[0] = s;
    if (s < Nc) {
        #pragma unroll
        for (int i = 0; i < 16; i++) {
            int m = lane + i * 32;
            bool pred = pcm[(size_t)m * Nc + s] != 0;
            unsigned bal = __ballot_sync(0xffffffffu, pred);
            int rank = __popc(bal & lt);
            if (pred && cnt + rank < MAXNB) adj[cnt + rank] = Nc + m;
            cnt += __popc(bal);
        }
    } else {
        const int* row = pcm + (size_t)(s - Nc) * Nc;
        #pragma unroll
        for (int i = 0; i < 32; i++) {
            int n = lane + i * 32;
            bool pred = row[n] != 0;
            unsigned bal = __ballot_sync(0xffffffffu, pred);
            int rank = __popc(bal & lt);
            if (pred && cnt + rank < MAXNB) adj[cnt + rank] = n;
            cnt += __popc(bal);
        }
    }
    if (lane == 0) g_adjcnt[s] = cnt < MAXNB ? cnt : MAXNB;
}

__global__ void k_xinit(const float* __restrict__ src_embed, const float* __restrict__ r_t) {
    int i = blockIdx.x * blockDim.x + threadIdx.x;
    if (i >= ROWS * Dc) return;
    int d = i & 127;
    int bs = i >> 7;
    int b = bs / Sc, s = bs % Sc;
    float node = (s < Nc) ? fabsf(r_t[(size_t)b * Nc + s]) : g_nodes[bs];
    g_x[i] = src_embed[s * Dc + d] * node * g_te[b * Dc + d];
}

// ---------------- weight transpose+split ----------------------------------------
__global__ void k_wsplit(const float* __restrict__ Wq, const float* __restrict__ Wk,
                         const float* __restrict__ Wv, const float* __restrict__ Wo,
                         const float* __restrict__ W1, const float* __restrict__ W2) {
    __shared__ float s[32][33];
    int bid = blockIdx.x;
    int l = bid / 192, tt = bid % 192;
    const float* src; int Nn, k0, n0; size_t dstBase; int dstLd;
    if (tt < 64) {
        int seg = tt >> 4, local = tt & 15;
        k0 = (local >> 2) * 32; n0 = (local & 3) * 32; Nn = 128; dstLd = 128;
        if      (seg == 0) { src = Wq + (size_t)l * 16384; dstBase = (size_t)l * PER_L; }
        else if (seg == 1) { src = Wk + (size_t)l * 16384; dstBase = (size_t)l * PER_L + 16384; }
        else if (seg == 2) { src = Wv + (size_t)l * 16384; dstBase = (size_t)l * PER_L + 32768; }
        else               { src = Wo + (size_t)l * 16384; dstBase = (size_t)l * PER_L + 49152; }
    } else if (tt < 128) {
        int local = tt - 64;
        k0 = (local >> 4) * 32; n0 = (local & 15) * 32; Nn = 512; dstLd = 128;
        src = W1 + (size_t)l * 65536; dstBase = (size_t)l * PER_L + 65536;
    } else {
        int local = tt - 128;
        k0 = (local >> 2) * 32; n0 = (local & 3) * 32; Nn = 128; dstLd = 512;
        src = W2 + (size_t)l * 65536; dstBase = (size_t)l * PER_L + 131072;
    }
    int tx = threadIdx.x & 31, ty = threadIdx.x >> 5;
    #pragma unroll
    for (int j = 0; j < 4; j++)
        s[ty + j * 8][tx] = src[(size_t)(k0 + ty + j * 8) * Nn + n0 + tx];
    __syncthreads();
    #pragma unroll
    for (int j = 0; j < 4; j++) {
        int n = n0 + ty + j * 8;
        float v = s[tx][ty + j * 8];
        __nv_bfloat16 hi, lo;
        split_bf16(v, hi, lo);
        size_t o = dstBase + (size_t)n * dstLd + k0 + tx;
        g_wThi[o] = hi;
        g_wTlo[o] = lo;
    }
}

// ---------------- bf16x3 GEMM with ldmatrix, BK=64, 2 CTAs/SM --------------------
// A[M,K] (row-major), B stored [Nn][K] (n-major). C[M,Nn].
// AMODE: 0 = A from (Ahi,Alo); 1 = LN(x,g,b); 2 = LN(x,g,b)*te
// EPI:   0 = store fp32; 1 = residual add fp32; 2 = relu -> split bf16
#define SWW 36                    // words per smem row (32 data + 4 pad)
#define A_WORDS (128 * SWW)       // 4608
#define B_WORDS (64 * SWW)        // 2304
#define SMEMB ((2 * A_WORDS + 2 * B_WORDS) * 4)   // 55296 bytes

__device__ __forceinline__ void mma_bf16(float* c, const unsigned* a, const unsigned* b) {
    asm volatile(
        "mma.sync.aligned.m16n8k16.row.col.f32.bf16.bf16.f32 "
        "{%0,%1,%2,%3}, {%4,%5,%6,%7}, {%8,%9}, {%0,%1,%2,%3};"
        : "+f"(c[0]), "+f"(c[1]), "+f"(c[2]), "+f"(c[3])
        : "r"(a[0]), "r"(a[1]), "r"(a[2]), "r"(a[3]), "r"(b[0]), "r"(b[1]));
}
__device__ __forceinline__ void ldsm4(unsigned* d, unsigned addr) {
    asm volatile("ldmatrix.sync.aligned.m8n8.x4.shared.b16 {%0,%1,%2,%3}, [%4];"
                 : "=r"(d[0]), "=r"(d[1]), "=r"(d[2]), "=r"(d[3]) : "r"(addr));
}

template <int AMODE, int EPI>
__global__ void __launch_bounds__(256, 2)
k_gemm(const float* __restrict__ Xf,
       const __nv_bfloat16* __restrict__ Ahi, const __nv_bfloat16* __restrict__ Alo,
       const float* __restrict__ gg, const float* __restrict__ bb,
       const __nv_bfloat16* __restrict__ Bhi, const __nv_bfloat16* __restrict__ Blo,
       float* __restrict__ C, __nv_bfloat16* __restrict__ Chi, __nv_bfloat16* __restrict__ Clo,
       int K, int Nn) {
    extern __shared__ unsigned smw[];
    unsigned* sAhi = smw;
    unsigned* sAlo = sAhi + A_WORDS;
    unsigned* sBhi = sAlo + A_WORDS;
    unsigned* sBlo = sBhi + B_WORDS;

    const int tid = threadIdx.x;
    const int lane = tid & 31, warp = tid >> 5;
    const int wm = (warp >> 1) * 32, wn = (warp & 1) * 32;
    const int g = lane >> 2, q4 = lane & 3;
    const int rowBase = blockIdx.y * 128, colBase = blockIdx.x * 64;

    // ldmatrix lane addresses (bytes). Row stride = 144 B.
    const unsigned aLaneOff = (unsigned)((wm + (lane & 15)) * SWW + (lane >> 4) * 4) * 4u;
    const unsigned bLaneOff = (unsigned)((wn + ((lane >> 4) & 1) * 8 + (lane & 7)) * SWW
                                         + ((lane >> 3) & 1) * 4) * 4u;
    const unsigned aHiBase = (unsigned)__cvta_generic_to_shared(sAhi) + aLaneOff;
    const unsigned aLoBase = (unsigned)__cvta_generic_to_shared(sAlo) + aLaneOff;
    const unsigned bHiBase = (unsigned)__cvta_generic_to_shared(sBhi) + bLaneOff;
    const unsigned bLoBase = (unsigned)__cvta_generic_to_shared(sBlo) + bLaneOff;

    float acc[2][4][4];
    #pragma unroll
    for (int mt = 0; mt < 2; mt++)
        #pragma unroll
        for (int nt = 0; nt < 4; nt++)
            #pragma unroll
            for (int i = 0; i < 4; i++) acc[mt][nt][i] = 0.0f;

    float4 gv, bv, tv;
    if (AMODE != 0) {
        gv = *(const float4*)&gg[lane * 4];
        bv = *(const float4*)&bb[lane * 4];
        if (AMODE == 2) {
            int bIdx = rowBase / Sc;
            tv = *(const float4*)&g_te[bIdx * Dc + lane * 4];
        }
    }

    for (int kt = 0; kt < K; kt += 64) {
        if (kt) __syncthreads();
        // ---- A slice: 128 rows x 64 bf16 ----
        if (AMODE == 0) {
            #pragma unroll
            for (int i = 0; i < 4; i++) {
                int idx = tid + i * 256;
                int r = idx >> 3, c = idx & 7;
                size_t goff = (size_t)(rowBase + r) * K + kt + c * 8;
                *(uint4*)&sAhi[r * SWW + c * 4] = *(const uint4*)(Ahi + goff);
                *(uint4*)&sAlo[r * SWW + c * 4] = *(const uint4*)(Alo + goff);
            }
        } else {
            // fused LN (recomputed per slice): warp covers 16 rows, lane = 4 cols
            bool writer = ((lane * 4) >= kt) && ((lane * 4) < kt + 64);
            int w = lane * 2 - (kt >> 1);
            #pragma unroll
            for (int p = 0; p < 16; p++) {
                int r = warp * 16 + p;
                float4 xv = *(const float4*)&Xf[(size_t)(rowBase + r) * 128 + lane * 4];
                float s1 = xv.x + xv.y + xv.z + xv.w;
                float s2 = xv.x * xv.x + xv.y * xv.y + xv.z * xv.z + xv.w * xv.w;
                #pragma unroll
                for (int o = 16; o > 0; o >>= 1) {
                    s1 += __shfl_xor_sync(0xffffffffu, s1, o);
                    s2 += __shfl_xor_sync(0xffffffffu, s2, o);
                }
                float mean = s1 * (1.0f / 128.0f);
                float var  = s2 * (1.0f / 128.0f) - mean * mean;
                float inv  = rsqrtf(var + 1e-5f);
                float o0 = (xv.x - mean) * inv * gv.x + bv.x;
                float o1 = (xv.y - mean) * inv * gv.y + bv.y;
                float o2 = (xv.z - mean) * inv * gv.z + bv.z;
                float o3 = (xv.w - mean) * inv * gv.w + bv.w;
                if (AMODE == 2) { o0 *= tv.x; o1 *= tv.y; o2 *= tv.z; o3 *= tv.w; }
                if (writer) {
                    sAhi[r * SWW + w]     = pack2hi(o0, o1);
                    sAhi[r * SWW + w + 1] = pack2hi(o2, o3);
                    sAlo[r * SWW + w]     = pack2lo(o0, o1);
                    sAlo[r * SWW + w + 1] = pack2lo(o2, o3);
                }
            }
        }
        // ---- B slice: 64 rows x 64 bf16 ----
        #pragma unroll
        for (int i = 0; i < 2; i++) {
            int idx = tid + i * 256;
            int r = idx >> 3, c = idx & 7;
            size_t goff = (size_t)(colBase + r) * K + kt + c * 8;
            *(uint4*)&sBhi[r * SWW + c * 4] = *(const uint4*)(Bhi + goff);
            *(uint4*)&sBlo[r * SWW + c * 4] = *(const uint4*)(Blo + goff);
        }
        __syncthreads();

        #pragma unroll
        for (int ks = 0; ks < 4; ks++) {
            const unsigned ko = ks * 32u;
            unsigned ah[2][4], al[2][4], bh[4][2], bl[4][2];
            #pragma unroll
            for (int mt = 0; mt < 2; mt++) {
                ldsm4(ah[mt], aHiBase + mt * 2304u + ko);
                ldsm4(al[mt], aLoBase + mt * 2304u + ko);
            }
            #pragma unroll
            for (int pr = 0; pr < 2; pr++) {
                unsigned t0[4], t1[4];
                ldsm4(t0, bHiBase + pr * 2304u + ko);
                ldsm4(t1, bLoBase + pr * 2304u + ko);
                bh[pr * 2][0] = t0[0]; bh[pr * 2][1] = t0[1];
                bh[pr * 2 + 1][0] = t0[2]; bh[pr * 2 + 1][1] = t0[3];
                bl[pr * 2][0] = t1[0]; bl[pr * 2][1] = t1[1];
                bl[pr * 2 + 1][0] = t1[2]; bl[pr * 2 + 1][1] = t1[3];
            }
            #pragma unroll
            for (int mt = 0; mt < 2; mt++)
                #pragma unroll
                for (int nt = 0; nt < 4; nt++) {
                    mma_bf16(acc[mt][nt], ah[mt], bh[nt]);
                    mma_bf16(acc[mt][nt], ah[mt], bl[nt]);
                    mma_bf16(acc[mt][nt], al[mt], bh[nt]);
                }
        }
    }

    // ---- epilogue ----
    #pragma unroll
    for (int mt = 0; mt < 2; mt++)
        #pragma unroll
        for (int nt = 0; nt < 4; nt++) {
            int r = rowBase + wm + mt * 16 + g;
            int c = colBase + wn + nt * 8 + q4 * 2;
            float* a = acc[mt][nt];
            if (EPI == 0) {
                *(float2*)&C[(size_t)r * Nn + c]       = make_float2(a[0], a[1]);
                *(float2*)&C[(size_t)(r + 8) * Nn + c] = make_float2(a[2], a[3]);
            } else if (EPI == 1) {
                float2 v0 = *(const float2*)&C[(size_t)r * Nn + c];
                float2 v1 = *(const float2*)&C[(size_t)(r + 8) * Nn + c];
                v0.x += a[0]; v0.y += a[1]; v1.x += a[2]; v1.y += a[3];
                *(float2*)&C[(size_t)r * Nn + c]       = v0;
                *(float2*)&C[(size_t)(r + 8) * Nn + c] = v1;
            } else {
                #pragma unroll
                for (int rr = 0; rr < 2; rr++) {
                    float v0 = fmaxf(a[rr * 2 + 0], 0.0f);
                    float v1 = fmaxf(a[rr * 2 + 1], 0.0f);
                    size_t o = (size_t)(r + rr * 8) * Nn + c;
                    *(unsigned*)&Chi[o] = pack2hi(v0, v1);
                    *(unsigned*)&Clo[o] = pack2lo(v0, v1);
                }
            }
        }
}

// ---------------- sparse masked attention ---------------------------------------
__global__ void k_attn(const float* __restrict__ qkv,
                       __nv_bfloat16* __restrict__ ohi, __nv_bfloat16* __restrict__ olo) {
    int bs = blockIdx.x;
    int b = bs / Sc, s = bs % Sc;
    int h = threadIdx.x >> 5, lane = threadIdx.x & 31;
    int cnt = g_adjcnt[s];

    const float* qp = qkv + (size_t)bs * 384 + h * HDc;
    float qr[HDc];
    #pragma unroll
    for (int d = 0; d < HDc; d++) qr[d] = qp[d];

    float sc0 = -1e30f, sc1 = -1e30f;
    int n0 = -1, n1 = -1;
    if (lane < cnt) {
        n0 = g_adj[s * MAXNB + lane];
        const float* kp = qkv + ((size_t)b * Sc + n0) * 384 + 128 + h * HDc;
        float dot = 0.0f;
        #pragma unroll
        for (int d = 0; d < HDc; d++) dot += qr[d] * kp[d];
        sc0 = dot * 0.25f;
    }
    if (lane + 32 < cnt) {
        n1 = g_adj[s * MAXNB + lane + 32];
        const float* kp = qkv + ((size_t)b * Sc + n1) * 384 + 128 + h * HDc;
        float dot = 0.0f;
        #pragma unroll
        for (int d = 0; d < HDc; d++) dot += qr[d] * kp[d];
        sc1 = dot * 0.25f;
    }

    float m = fmaxf(sc0, sc1);
    #pragma unroll
    for (int off = 16; off > 0; off >>= 1) m = fmaxf(m, __shfl_xor_sync(0xffffffffu, m, off));
    float p0 = (n0 >= 0) ? __expf(sc0 - m) : 0.0f;
    float p1 = (n1 >= 0) ? __expf(sc1 - m) : 0.0f;
    float ps = p0 + p1;
    #pragma unroll
    for (int off = 16; off > 0; off >>= 1) ps += __shfl_xor_sync(0xffffffffu, ps, off);

    float acc[HDc] = {};
    if (n0 >= 0) {
        const float* vp = qkv + ((size_t)b * Sc + n0) * 384 + 256 + h * HDc;
        #pragma unroll
        for (int d = 0; d < HDc; d++) acc[d] += p0 * vp[d];
    }
    if (n1 >= 0) {
        const float* vp = qkv + ((size_t)b * Sc + n1) * 384 + 256 + h * HDc;
        #pragma unroll
        for (int d = 0; d < HDc; d++) acc[d] += p1 * vp[d];
    }
    #pragma unroll
    for (int d = 0; d < HDc; d++)
        #pragma unroll
        for (int off = 16; off > 0; off >>= 1)
            acc[d] += __shfl_xor_sync(0xffffffffu, acc[d], off);

    if (lane == 0) {
        float inv = 1.0f / ps;
        #pragma unroll
        for (int d = 0; d < HDc; d += 2) {
            float v0 = acc[d] * inv, v1 = acc[d + 1] * inv;
            size_t o = (size_t)bs * Dc + h * HDc + d;
            *(unsigned*)&ohi[o] = pack2hi(v0, v1);
            *(unsigned*)&olo[o] = pack2lo(v0, v1);
        }
    }
}

// ---------------- final projection -----------------------------------------------
__global__ void k_out(const float* __restrict__ fc_w, const float* __restrict__ fc_b,
                      float* __restrict__ out) {
    int row = blockIdx.x * 8 + (threadIdx.x >> 5);
    if (row >= ROWS) return;
    int lane = threadIdx.x & 31;
    float sum = 0.0f;
    #pragma unroll
    for (int d = lane; d < Dc; d += 32) sum += g_x[(size_t)row * Dc + d] * fc_w[d];
    #pragma unroll
    for (int off = 16; off > 0; off >>= 1) sum += __shfl_xor_sync(0xffffffffu, sum, off);
    if (lane == 0) out[row] = sum + fc_b[0];
}

// ---------------- launcher ---------------------------------------------------------
extern "C" void kernel_launch(void* const* d_in, const int* in_sizes, int n_in,
                              void* d_out, int out_size) {
    const float* r_t        = (const float*)d_in[0];
    const int*   t          = (const int*)  d_in[1];
    const int*   pcm        = (const int*)  d_in[2];
    const float* src_embed  = (const float*)d_in[4];
    const float* time_table = (const float*)d_in[5];
    const float* Wq = (const float*)d_in[6];
    const float* Wk = (const float*)d_in[7];
    const float* Wv = (const float*)d_in[8];
    const float* Wo = (const float*)d_in[9];
    const float* W1 = (const float*)d_in[10];
    const float* W2 = (const float*)d_in[11];
    const float* g1 = (const float*)d_in[12];
    const float* b1 = (const float*)d_in[13];
    const float* g2 = (const float*)d_in[14];
    const float* b2 = (const float*)d_in[15];
    const float* fc_w = (const float*)d_in[16];
    const float* fc_b = (const float*)d_in[17];
    float* out = (float*)d_out;

    float *px, *pqkv;
    __nv_bfloat16 *whi, *wlo, *ohi, *olo, *fhi, *flo;
    cudaGetSymbolAddress((void**)&px,   g_x);
    cudaGetSymbolAddress((void**)&pqkv, g_qkv);
    cudaGetSymbolAddress((void**)&whi,  g_wThi);
    cudaGetSymbolAddress((void**)&wlo,  g_wTlo);
    cudaGetSymbolAddress((void**)&ohi,  g_ohi);
    cudaGetSymbolAddress((void**)&olo,  g_olo);
    cudaGetSymbolAddress((void**)&fhi,  g_fhi);
    cudaGetSymbolAddress((void**)&flo,  g_flo);

    static int smemSet = 0;
    if (!smemSet) {
        cudaFuncSetAttribute(k_gemm<1,0>, cudaFuncAttributeMaxDynamicSharedMemorySize, SMEMB);
        cudaFuncSetAttribute(k_gemm<0,1>, cudaFuncAttributeMaxDynamicSharedMemorySize, SMEMB);
        cudaFuncSetAttribute(k_gemm<2,2>, cudaFuncAttributeMaxDynamicSharedMemorySize, SMEMB);
        smemSet = 1;
    }

    k_te    <<<(Bc * Dc + 255) / 256, 256>>>(t, time_table);
    k_nodes <<<(Bc * Mc + 7) / 8, 256>>>(r_t, pcm);
    k_adj   <<<(Sc + 7) / 8, 256>>>(pcm);
    k_xinit <<<(ROWS * Dc + 255) / 256, 256>>>(src_embed, r_t);
    k_wsplit<<<Lc * 192, 256>>>(Wq, Wk, Wv, Wo, W1, W2);

    dim3 gQKV(6, 96);
    dim3 gD  (2, 96);
    dim3 gF  (8, 96);

    for (int l = 0; l < Lc; l++) {
        const __nv_bfloat16* lwh = whi + (size_t)l * PER_L;
        const __nv_bfloat16* lwl = wlo + (size_t)l * PER_L;

        k_gemm<1,0><<<gQKV, 256, SMEMB>>>(px, nullptr, nullptr, g1 + l * Dc, b1 + l * Dc,
                                          lwh, lwl, pqkv, nullptr, nullptr, 128, 384);
        k_attn<<<ROWS, 256>>>(pqkv, ohi, olo);
        k_gemm<0,1><<<gD, 256, SMEMB>>>(nullptr, ohi, olo, nullptr, nullptr,
                                        lwh + 49152, lwl + 49152, px, nullptr, nullptr, 128, 128);
        k_gemm<2,2><<<gF, 256, SMEMB>>>(px, nullptr, nullptr, g2 + l * Dc, b2 + l * Dc,
                                        lwh + 65536, lwl + 65536, nullptr, fhi, flo, 128, 512);
        k_gemm<0,1><<<gD, 256, SMEMB>>>(nullptr, fhi, flo, nullptr, nullptr,
                                        lwh + 131072, lwl + 131072, px, nullptr, nullptr, 512, 128);
    }

    k_out<<<(ROWS + 7) / 8, 256>>>(fc_w, fc_b, out);
}

// round 8
// speedup vs baseline: 2.5211x; 1.9429x over previous
#include <cuda_runtime.h>
#include <cuda_bf16.h>
#include <math.h>

#define Bc      8
#define Nc      1024
#define Mc      512
#define Dc      128
#define Lc      6
#define DFFc    512
#define Sc      1536
#define HDc     16
#define MAXNB   64
#define ROWS    12288
#define PER_L   196608

// ---------------- scratch ------------------------------------------------------
__device__ float g_x  [ROWS * Dc];
__device__ float g_qkv[ROWS * 384];
__device__ float g_te [Bc * Dc];
__device__ float g_nodes[ROWS];
__device__ int   g_adj[Sc * MAXNB];
__device__ int   g_adjcnt[Sc];

__device__ __nv_bfloat16 g_wThi[Lc * PER_L];
__device__ __nv_bfloat16 g_wTlo[Lc * PER_L];
__device__ __nv_bfloat16 g_ohi[ROWS * Dc];
__device__ __nv_bfloat16 g_olo[ROWS * Dc];
__device__ __nv_bfloat16 g_fhi[ROWS * DFFc];
__device__ __nv_bfloat16 g_flo[ROWS * DFFc];

__device__ __forceinline__ void split_bf16(float v, __nv_bfloat16& hi, __nv_bfloat16& lo) {
    hi = __float2bfloat16_rn(v);
    lo = __float2bfloat16_rn(v - __bfloat162float(hi));
}
__device__ __forceinline__ unsigned pack2hi(float a, float b) {
    __nv_bfloat162 p; p.x = __float2bfloat16_rn(a); p.y = __float2bfloat16_rn(b);
    return *(unsigned*)&p;
}
__device__ __forceinline__ unsigned pack2lo(float a, float b) {
    __nv_bfloat162 p;
    p.x = __float2bfloat16_rn(a - __bfloat162float(__float2bfloat16_rn(a)));
    p.y = __float2bfloat16_rn(b - __bfloat162float(__float2bfloat16_rn(b)));
    return *(unsigned*)&p;
}

// ---------------- merged init: te + syndrome nodes + adjacency ------------------
// blocks 0..511: nodes (warp per (b,m)); 512..703: adj (warp per s); 704: te
__global__ void k_init0(const int* __restrict__ t, const float* __restrict__ time_table,
                        const float* __restrict__ r_t, const int* __restrict__ pcm) {
    int blk = blockIdx.x;
    int lane = threadIdx.x & 31;
    if (blk < 512) {
        int w = blk * 8 + (threadIdx.x >> 5);          // (b, m)
        int b = w >> 9, m = w & 511;
        int cnt = 0;
        #pragma unroll
        for (int i = 0; i < 32; i++) {
            int col = lane + i * 32;
            bool pred = (pcm[(size_t)m * Nc + col] != 0) && (r_t[(size_t)b * Nc + col] < 0.0f);
            cnt += __popc(__ballot_sync(0xffffffffu, pred));
        }
        if (lane == 0) g_nodes[(size_t)b * Sc + Nc + m] = (float)(cnt & 1);
    } else if (blk < 704) {
        int s = (blk - 512) * 8 + (threadIdx.x >> 5);
        unsigned lt = (1u << lane) - 1u;
        int* adj = g_adj + s * MAXNB;
        int cnt = 1;
        if (lane == 0) adj[0] = s;
        if (s < Nc) {
            #pragma unroll
            for (int i = 0; i < 16; i++) {
                int m = lane + i * 32;
                bool pred = pcm[(size_t)m * Nc + s] != 0;
                unsigned bal = __ballot_sync(0xffffffffu, pred);
                int rank = __popc(bal & lt);
                if (pred && cnt + rank < MAXNB) adj[cnt + rank] = Nc + m;
                cnt += __popc(bal);
            }
        } else {
            const int* row = pcm + (size_t)(s - Nc) * Nc;
            #pragma unroll
            for (int i = 0; i < 32; i++) {
                int n = lane + i * 32;
                bool pred = row[n] != 0;
                unsigned bal = __ballot_sync(0xffffffffu, pred);
                int rank = __popc(bal & lt);
                if (pred && cnt + rank < MAXNB) adj[cnt + rank] = n;
                cnt += __popc(bal);
            }
        }
        if (lane == 0) g_adjcnt[s] = cnt < MAXNB ? cnt : MAXNB;
    } else {
        #pragma unroll
        for (int i = threadIdx.x; i < Bc * Dc; i += 256) {
            int b = i >> 7, d = i & 127;
            g_te[i] = time_table[t[b] * Dc + d];
        }
    }
}

__global__ void k_xinit(const float* __restrict__ src_embed, const float* __restrict__ r_t) {
    int i = blockIdx.x * blockDim.x + threadIdx.x;
    if (i >= ROWS * Dc) return;
    int d = i & 127;
    int bs = i >> 7;
    int b = bs / Sc, s = bs % Sc;
    float node = (s < Nc) ? fabsf(r_t[(size_t)b * Nc + s]) : g_nodes[bs];
    g_x[i] = src_embed[s * Dc + d] * node * g_te[b * Dc + d];
}

// ---------------- weight transpose+split ----------------------------------------
__global__ void k_wsplit(const float* __restrict__ Wq, const float* __restrict__ Wk,
                         const float* __restrict__ Wv, const float* __restrict__ Wo,
                         const float* __restrict__ W1, const float* __restrict__ W2) {
    __shared__ float s[32][33];
    int bid = blockIdx.x;
    int l = bid / 192, tt = bid % 192;
    const float* src; int Nn, k0, n0; size_t dstBase; int dstLd;
    if (tt < 64) {
        int seg = tt >> 4, local = tt & 15;
        k0 = (local >> 2) * 32; n0 = (local & 3) * 32; Nn = 128; dstLd = 128;
        if      (seg == 0) { src = Wq + (size_t)l * 16384; dstBase = (size_t)l * PER_L; }
        else if (seg == 1) { src = Wk + (size_t)l * 16384; dstBase = (size_t)l * PER_L + 16384; }
        else if (seg == 2) { src = Wv + (size_t)l * 16384; dstBase = (size_t)l * PER_L + 32768; }
        else               { src = Wo + (size_t)l * 16384; dstBase = (size_t)l * PER_L + 49152; }
    } else if (tt < 128) {
        int local = tt - 64;
        k0 = (local >> 4) * 32; n0 = (local & 15) * 32; Nn = 512; dstLd = 128;
        src = W1 + (size_t)l * 65536; dstBase = (size_t)l * PER_L + 65536;
    } else {
        int local = tt - 128;
        k0 = (local >> 2) * 32; n0 = (local & 3) * 32; Nn = 128; dstLd = 512;
        src = W2 + (size_t)l * 65536; dstBase = (size_t)l * PER_L + 131072;
    }
    int tx = threadIdx.x & 31, ty = threadIdx.x >> 5;
    #pragma unroll
    for (int j = 0; j < 4; j++)
        s[ty + j * 8][tx] = src[(size_t)(k0 + ty + j * 8) * Nn + n0 + tx];
    __syncthreads();
    #pragma unroll
    for (int j = 0; j < 4; j++) {
        int n = n0 + ty + j * 8;
        float v = s[tx][ty + j * 8];
        __nv_bfloat16 hi, lo;
        split_bf16(v, hi, lo);
        size_t o = dstBase + (size_t)n * dstLd + k0 + tx;
        g_wThi[o] = hi;
        g_wTlo[o] = lo;
    }
}

// ---------------- fused LN + bf16x3 tensor-core GEMM (round-4 core) --------------
// BM=128, BN=16*NT, K-slices of 128 resident in smem.
// AMODE: 0 = A from (Ahi,Alo); 1 = LN(x,g,b); 2 = LN(x,g,b)*te
// EPI:   0 = store fp32; 1 = residual add fp32; 2 = relu -> split bf16
#define SW 68
#define A_WORDS (128 * SW)
#define B_WORDS (64 * SW)
#define SMEMB ((2 * A_WORDS + 2 * B_WORDS) * 4)

__device__ __forceinline__ void mma_bf16(float* c, const unsigned* a, const unsigned* b) {
    asm volatile(
        "mma.sync.aligned.m16n8k16.row.col.f32.bf16.bf16.f32 "
        "{%0,%1,%2,%3}, {%4,%5,%6,%7}, {%8,%9}, {%0,%1,%2,%3};"
        : "+f"(c[0]), "+f"(c[1]), "+f"(c[2]), "+f"(c[3])
        : "r"(a[0]), "r"(a[1]), "r"(a[2]), "r"(a[3]), "r"(b[0]), "r"(b[1]));
}

template <int AMODE, int EPI, int NT>   // NT = n-tiles per warp (BN = 16*NT)
__global__ void __launch_bounds__(256)
k_gemm(const float* __restrict__ Xf,
       const __nv_bfloat16* __restrict__ Ahi, const __nv_bfloat16* __restrict__ Alo,
       const float* __restrict__ gg, const float* __restrict__ bb,
       const __nv_bfloat16* __restrict__ Bhi, const __nv_bfloat16* __restrict__ Blo,
       float* __restrict__ C, __nv_bfloat16* __restrict__ Chi, __nv_bfloat16* __restrict__ Clo,
       int K, int Nn) {
    extern __shared__ unsigned smw[];
    unsigned* sAhi = smw;
    unsigned* sAlo = sAhi + A_WORDS;
    unsigned* sBhi = sAlo + A_WORDS;
    unsigned* sBlo = sBhi + B_WORDS;

    const int tid = threadIdx.x;
    const int lane = tid & 31, warp = tid >> 5;
    const int wm = (warp >> 1) * 32, wn = (warp & 1) * (NT * 8);
    const int g = lane >> 2, q4 = lane & 3;
    const int BN = 16 * NT;
    const int rowBase = blockIdx.y * 128, colBase = blockIdx.x * BN;

    float acc[2][NT][4];
    #pragma unroll
    for (int mt = 0; mt < 2; mt++)
        #pragma unroll
        for (int nt = 0; nt < NT; nt++)
            #pragma unroll
            for (int i = 0; i < 4; i++) acc[mt][nt][i] = 0.0f;

    float4 gv, bv, tv;
    if (AMODE != 0) {
        gv = *(const float4*)&gg[lane * 4];
        bv = *(const float4*)&bb[lane * 4];
        if (AMODE == 2) {
            int bIdx = rowBase / Sc;
            tv = *(const float4*)&g_te[bIdx * Dc + lane * 4];
        }
    }

    for (int kt = 0; kt < K; kt += 128) {
        if (kt) __syncthreads();
        // ---- A slice ----
        if (AMODE == 0) {
            #pragma unroll
            for (int i = 0; i < 8; i++) {
                int t = tid + i * 256;
                int r = t >> 4, c = t & 15;
                size_t goff = (size_t)(rowBase + r) * K + kt + c * 8;
                *(uint4*)&sAhi[r * SW + c * 4] = *(const uint4*)(Ahi + goff);
                *(uint4*)&sAlo[r * SW + c * 4] = *(const uint4*)(Alo + goff);
            }
        } else {
            #pragma unroll
            for (int p = 0; p < 16; p++) {
                int r = warp * 16 + p;
                float4 xv = *(const float4*)&Xf[(size_t)(rowBase + r) * 128 + lane * 4];
                float s1 = xv.x + xv.y + xv.z + xv.w;
                float s2 = xv.x * xv.x + xv.y * xv.y + xv.z * xv.z + xv.w * xv.w;
                #pragma unroll
                for (int o = 16; o > 0; o >>= 1) {
                    s1 += __shfl_xor_sync(0xffffffffu, s1, o);
                    s2 += __shfl_xor_sync(0xffffffffu, s2, o);
                }
                float mean = s1 * (1.0f / 128.0f);
                float var  = s2 * (1.0f / 128.0f) - mean * mean;
                float inv  = rsqrtf(var + 1e-5f);
                float o0 = (xv.x - mean) * inv * gv.x + bv.x;
                float o1 = (xv.y - mean) * inv * gv.y + bv.y;
                float o2 = (xv.z - mean) * inv * gv.z + bv.z;
                float o3 = (xv.w - mean) * inv * gv.w + bv.w;
                if (AMODE == 2) { o0 *= tv.x; o1 *= tv.y; o2 *= tv.z; o3 *= tv.w; }
                sAhi[r * SW + lane * 2]     = pack2hi(o0, o1);
                sAhi[r * SW + lane * 2 + 1] = pack2hi(o2, o3);
                sAlo[r * SW + lane * 2]     = pack2lo(o0, o1);
                sAlo[r * SW + lane * 2 + 1] = pack2lo(o2, o3);
            }
        }
        // ---- B slice: BN rows x 128 bf16 ----
        #pragma unroll
        for (int i = 0; i < NT; i++) {
            int t = tid + i * 256;
            int n = t >> 4, c = t & 15;
            size_t goff = (size_t)(colBase + n) * K + kt + c * 8;
            *(uint4*)&sBhi[n * SW + c * 4] = *(const uint4*)(Bhi + goff);
            *(uint4*)&sBlo[n * SW + c * 4] = *(const uint4*)(Blo + goff);
        }
        __syncthreads();

        #pragma unroll
        for (int ks = 0; ks < 8; ks++) {
            const int w0 = ks * 8 + q4;
            unsigned ah[2][4], al[2][4], bh[NT][2], bl[NT][2];
            #pragma unroll
            for (int mt = 0; mt < 2; mt++) {
                int r0 = wm + mt * 16 + g;
                ah[mt][0] = sAhi[r0 * SW + w0];
                ah[mt][1] = sAhi[(r0 + 8) * SW + w0];
                ah[mt][2] = sAhi[r0 * SW + w0 + 4];
                ah[mt][3] = sAhi[(r0 + 8) * SW + w0 + 4];
                al[mt][0] = sAlo[r0 * SW + w0];
                al[mt][1] = sAlo[(r0 + 8) * SW + w0];
                al[mt][2] = sAlo[r0 * SW + w0 + 4];
                al[mt][3] = sAlo[(r0 + 8) * SW + w0 + 4];
            }
            #pragma unroll
            for (int nt = 0; nt < NT; nt++) {
                int n0 = wn + nt * 8 + g;
                bh[nt][0] = sBhi[n0 * SW + w0];
                bh[nt][1] = sBhi[n0 * SW + w0 + 4];
                bl[nt][0] = sBlo[n0 * SW + w0];
                bl[nt][1] = sBlo[n0 * SW + w0 + 4];
            }
            #pragma unroll
            for (int mt = 0; mt < 2; mt++)
                #pragma unroll
                for (int nt = 0; nt < NT; nt++) {
                    mma_bf16(acc[mt][nt], ah[mt], bh[nt]);
                    mma_bf16(acc[mt][nt], ah[mt], bl[nt]);
                    mma_bf16(acc[mt][nt], al[mt], bh[nt]);
                }
        }
    }

    // ---- epilogue ----
    #pragma unroll
    for (int mt = 0; mt < 2; mt++)
        #pragma unroll
        for (int nt = 0; nt < NT; nt++) {
            int r = rowBase + wm + mt * 16 + g;
            int c = colBase + wn + nt * 8 + q4 * 2;
            float* a = acc[mt][nt];
            if (EPI == 0) {
                *(float2*)&C[(size_t)r * Nn + c]       = make_float2(a[0], a[1]);
                *(float2*)&C[(size_t)(r + 8) * Nn + c] = make_float2(a[2], a[3]);
            } else if (EPI == 1) {
                float2 v0 = *(const float2*)&C[(size_t)r * Nn + c];
                float2 v1 = *(const float2*)&C[(size_t)(r + 8) * Nn + c];
                v0.x += a[0]; v0.y += a[1]; v1.x += a[2]; v1.y += a[3];
                *(float2*)&C[(size_t)r * Nn + c]       = v0;
                *(float2*)&C[(size_t)(r + 8) * Nn + c] = v1;
            } else {
                #pragma unroll
                for (int rr = 0; rr < 2; rr++) {
                    float v0 = fmaxf(a[rr * 2 + 0], 0.0f);
                    float v1 = fmaxf(a[rr * 2 + 1], 0.0f);
                    size_t o = (size_t)(r + rr * 8) * Nn + c;
                    *(unsigned*)&Chi[o] = pack2hi(v0, v1);
                    *(unsigned*)&Clo[o] = pack2lo(v0, v1);
                }
            }
        }
}

// ---------------- sparse attention: warp per row, all heads, online softmax ------
__global__ void __launch_bounds__(256)
k_attn(const float* __restrict__ qkv,
       __nv_bfloat16* __restrict__ ohi, __nv_bfloat16* __restrict__ olo) {
    int warp = threadIdx.x >> 5, lane = threadIdx.x & 31;
    int bs = blockIdx.x * 8 + warp;
    int b = bs / Sc, s = bs % Sc;
    int cnt = g_adjcnt[s];
    const int* adj = g_adj + s * MAXNB;

    // lane covers dims [lane*4, lane*4+4) of head (lane>>2)
    float4 qv = *(const float4*)&qkv[(size_t)bs * 384 + lane * 4];

    float m = -1e30f, l = 0.0f;
    float4 acc = make_float4(0.0f, 0.0f, 0.0f, 0.0f);

    for (int j = 0; j < cnt; j++) {
        int n = adj[j];
        const float* kr = qkv + ((size_t)b * Sc + n) * 384 + 128;
        float4 kv = *(const float4*)&kr[lane * 4];
        float d = qv.x * kv.x + qv.y * kv.y + qv.z * kv.z + qv.w * kv.w;
        d += __shfl_xor_sync(0xffffffffu, d, 1);
        d += __shfl_xor_sync(0xffffffffu, d, 2);
        float sc = d * 0.25f;                    // 1/sqrt(16)
        float mn = fmaxf(m, sc);
        float scale = __expf(m - mn);
        float p = __expf(sc - mn);
        l = l * scale + p;
        float4 vv = *(const float4*)&kr[128 + lane * 4];
        acc.x = acc.x * scale + p * vv.x;
        acc.y = acc.y * scale + p * vv.y;
        acc.z = acc.z * scale + p * vv.z;
        acc.w = acc.w * scale + p * vv.w;
        m = mn;
    }

    float inv = 1.0f / l;
    float v0 = acc.x * inv, v1 = acc.y * inv, v2 = acc.z * inv, v3 = acc.w * inv;
    size_t o = (size_t)bs * Dc + lane * 4;
    *(unsigned*)&ohi[o]     = pack2hi(v0, v1);
    *(unsigned*)&ohi[o + 2] = pack2hi(v2, v3);
    *(unsigned*)&olo[o]     = pack2lo(v0, v1);
    *(unsigned*)&olo[o + 2] = pack2lo(v2, v3);
}

// ---------------- final projection -----------------------------------------------
__global__ void k_out(const float* __restrict__ fc_w, const float* __restrict__ fc_b,
                      float* __restrict__ out) {
    int row = blockIdx.x * 8 + (threadIdx.x >> 5);
    if (row >= ROWS) return;
    int lane = threadIdx.x & 31;
    float sum = 0.0f;
    #pragma unroll
    for (int d = lane; d < Dc; d += 32) sum += g_x[(size_t)row * Dc + d] * fc_w[d];
    #pragma unroll
    for (int off = 16; off > 0; off >>= 1) sum += __shfl_xor_sync(0xffffffffu, sum, off);
    if (lane == 0) out[row] = sum + fc_b[0];
}

// ---------------- launcher ---------------------------------------------------------
extern "C" void kernel_launch(void* const* d_in, const int* in_sizes, int n_in,
                              void* d_out, int out_size) {
    const float* r_t        = (const float*)d_in[0];
    const int*   t          = (const int*)  d_in[1];
    const int*   pcm        = (const int*)  d_in[2];
    const float* src_embed  = (const float*)d_in[4];
    const float* time_table = (const float*)d_in[5];
    const float* Wq = (const float*)d_in[6];
    const float* Wk = (const float*)d_in[7];
    const float* Wv = (const float*)d_in[8];
    const float* Wo = (const float*)d_in[9];
    const float* W1 = (const float*)d_in[10];
    const float* W2 = (const float*)d_in[11];
    const float* g1 = (const float*)d_in[12];
    const float* b1 = (const float*)d_in[13];
    const float* g2 = (const float*)d_in[14];
    const float* b2 = (const float*)d_in[15];
    const float* fc_w = (const float*)d_in[16];
    const float* fc_b = (const float*)d_in[17];
    float* out = (float*)d_out;

    float *px, *pqkv;
    __nv_bfloat16 *whi, *wlo, *ohi, *olo, *fhi, *flo;
    cudaGetSymbolAddress((void**)&px,   g_x);
    cudaGetSymbolAddress((void**)&pqkv, g_qkv);
    cudaGetSymbolAddress((void**)&whi,  g_wThi);
    cudaGetSymbolAddress((void**)&wlo,  g_wTlo);
    cudaGetSymbolAddress((void**)&ohi,  g_ohi);
    cudaGetSymbolAddress((void**)&olo,  g_olo);
    cudaGetSymbolAddress((void**)&fhi,  g_fhi);
    cudaGetSymbolAddress((void**)&flo,  g_flo);

    static int smemSet = 0;
    if (!smemSet) {
        cudaFuncSetAttribute(k_gemm<1,0,4>, cudaFuncAttributeMaxDynamicSharedMemorySize, SMEMB);
        cudaFuncSetAttribute(k_gemm<0,1,2>, cudaFuncAttributeMaxDynamicSharedMemorySize, SMEMB);
        cudaFuncSetAttribute(k_gemm<2,2,4>, cudaFuncAttributeMaxDynamicSharedMemorySize, SMEMB);
        smemSet = 1;
    }

    k_init0<<<705, 256>>>(t, time_table, r_t, pcm);
    k_xinit<<<(ROWS * Dc + 255) / 256, 256>>>(src_embed, r_t);
    k_wsplit<<<Lc * 192, 256>>>(Wq, Wk, Wv, Wo, W1, W2);

    dim3 gQKV(6, 96);    // BN=64
    dim3 gD32(4, 96);    // BN=32 for O-proj / W2 (384 CTAs)
    dim3 gF  (8, 96);    // BN=64

    for (int l = 0; l < Lc; l++) {
        const __nv_bfloat16* lwh = whi + (size_t)l * PER_L;
        const __nv_bfloat16* lwl = wlo + (size_t)l * PER_L;

        k_gemm<1,0,4><<<gQKV, 256, SMEMB>>>(px, nullptr, nullptr, g1 + l * Dc, b1 + l * Dc,
                                            lwh, lwl, pqkv, nullptr, nullptr, 128, 384);
        k_attn<<<ROWS / 8, 256>>>(pqkv, ohi, olo);
        k_gemm<0,1,2><<<gD32, 256, SMEMB>>>(nullptr, ohi, olo, nullptr, nullptr,
                                            lwh + 49152, lwl + 49152, px, nullptr, nullptr, 128, 128);
        k_gemm<2,2,4><<<gF, 256, SMEMB>>>(px, nullptr, nullptr, g2 + l * Dc, b2 + l * Dc,
                                          lwh + 65536, lwl + 65536, nullptr, fhi, flo, 128, 512);
        k_gemm<0,1,2><<<gD32, 256, SMEMB>>>(nullptr, fhi, flo, nullptr, nullptr,
                                            lwh + 131072, lwl + 131072, px, nullptr, nullptr, 512, 128);
    }

    k_out<<<(ROWS + 7) / 8, 256>>>(fc_w, fc_b, out);
}